// round 15
// baseline (speedup 1.0000x reference)
#include <cuda_runtime.h>
#include <cuda_fp16.h>
#include <stdint.h>

#define N_NODES 50000
#define N_EDGES 600000
#define D 128
#define EPS 1e-5f
#define SCAN_BLOCKS 49   // ceil(50000/1024)

// ---------------- scratch (device globals; no allocations allowed) ----------
__device__ __half g_hn_h[N_NODES * D];   // layernormed features (fp16)
__device__ __half g_W_h[D * 2 * D];      // W fp16 (row-major [128][256])
__device__ int    g_counters[2 * N_NODES];  // [deg_in | deg_out]; self-zeroing
__device__ float  g_inv_in[N_NODES];
__device__ float  g_inv_out[N_NODES];
__device__ int    g_rowstart[N_NODES];   // block-local exclusive scan of deg_in
__device__ int    g_blocksum[SCAN_BLOCKS];
__device__ int    g_blockoff[SCAN_BLOCKS];
__device__ int    g_epos[N_EDGES];       // per-edge rank within destination
__device__ int    g_csr_src[N_EDGES];

#define DEG_IN  (g_counters)
#define DEG_OUT (g_counters + N_NODES)

__device__ __forceinline__ int row_begin(int w) {
    return g_rowstart[w] + g_blockoff[w >> 10];
}

__device__ __forceinline__ void cp_async16(void* smem, const void* gmem) {
    uint32_t s = (uint32_t)__cvta_generic_to_shared(smem);
    asm volatile("cp.async.cg.shared.global [%0], [%1], 16;" :: "r"(s), "l"(gmem));
}
#define CP_COMMIT() asm volatile("cp.async.commit_group;")
#define CP_WAIT(n)  asm volatile("cp.async.wait_group %0;" :: "n"(n))

// ---------------- K1: degree counts + per-edge rank --------------------------
__global__ void k_count(const int* __restrict__ src,
                        const int* __restrict__ dst) {
    int i = blockIdx.x * blockDim.x + threadIdx.x;
    if (i < N_EDGES) {
        atomicAdd(&DEG_OUT[__ldg(&src[i])], 1);
        g_epos[i] = atomicAdd(&DEG_IN[__ldg(&dst[i])], 1);
    }
}

// ---------------- K1b: convert W to fp16 -------------------------------------
__global__ void k_convw(const float* __restrict__ W) {
    int i = blockIdx.x * blockDim.x + threadIdx.x;   // over float4 groups
    if (i < (D * 2 * D) / 4) {
        float4 v = *(const float4*)&W[i * 4];
        __half2 h0 = __float22half2_rn(make_float2(v.x, v.y));
        __half2 h1 = __float22half2_rn(make_float2(v.z, v.w));
        uint2 p;
        p.x = *(uint32_t*)&h0;
        p.y = *(uint32_t*)&h1;
        *(uint2*)&g_W_h[i * 4] = p;
    }
}

// ---------------- K2: LayerNorm (warp per row) -> fp16 (pure) ----------------
__global__ void k_layernorm(const float* __restrict__ h,
                            const float* __restrict__ gamma,
                            const float* __restrict__ beta) {
    int warp = (blockIdx.x * blockDim.x + threadIdx.x) >> 5;
    int lane = threadIdx.x & 31;
    if (warp >= N_NODES) return;

    float4 v = ((const float4*)h)[warp * 32 + lane];
    float s  = v.x + v.y + v.z + v.w;
    float sq = v.x * v.x + v.y * v.y + v.z * v.z + v.w * v.w;
    #pragma unroll
    for (int off = 16; off > 0; off >>= 1) {
        s  += __shfl_xor_sync(0xFFFFFFFF, s,  off);
        sq += __shfl_xor_sync(0xFFFFFFFF, sq, off);
    }
    float mu  = s * (1.0f / D);
    float var = sq * (1.0f / D) - mu * mu;
    float rs  = rsqrtf(var + EPS);

    float4 g = ((const float4*)gamma)[lane];
    float4 b = ((const float4*)beta)[lane];
    float ox = (v.x - mu) * rs * g.x + b.x;
    float oy = (v.y - mu) * rs * g.y + b.y;
    float oz = (v.z - mu) * rs * g.z + b.z;
    float ow = (v.w - mu) * rs * g.w + b.w;

    __half2 h0 = __float22half2_rn(make_float2(ox, oy));
    __half2 h1 = __float22half2_rn(make_float2(oz, ow));
    uint2 pack;
    pack.x = *(uint32_t*)&h0;
    pack.y = *(uint32_t*)&h1;
    ((uint2*)g_hn_h)[warp * 32 + lane] = pack;
}

// ---------------- K3a: block scan of deg_in + inv-sqrt; self-zero DEG --------
__global__ __launch_bounds__(1024)
void k_scan_local() {
    __shared__ int warp_sums[32];
    int t = threadIdx.x;
    int i = blockIdx.x * 1024 + t;
    int lane = t & 31;
    int wid = t >> 5;

    int v = 0;
    if (i < N_NODES) {
        v = DEG_IN[i];
        int dout = DEG_OUT[i];
        g_inv_in[i]  = rsqrtf((float)(v    < 1 ? 1 : v));
        g_inv_out[i] = rsqrtf((float)(dout < 1 ? 1 : dout));
        DEG_IN[i]  = 0;     // restore zeros for the next replay (deterministic)
        DEG_OUT[i] = 0;
    }
    int incl = v;
    #pragma unroll
    for (int off = 1; off < 32; off <<= 1) {
        int n = __shfl_up_sync(0xFFFFFFFF, incl, off);
        if (lane >= off) incl += n;
    }
    if (lane == 31) warp_sums[wid] = incl;
    __syncthreads();
    if (wid == 0) {
        int ws = warp_sums[lane];
        int wi = ws;
        #pragma unroll
        for (int off = 1; off < 32; off <<= 1) {
            int n = __shfl_up_sync(0xFFFFFFFF, wi, off);
            if (lane >= off) wi += n;
        }
        warp_sums[lane] = wi - ws;   // exclusive warp offset
        if (lane == 31) g_blocksum[blockIdx.x] = wi;
    }
    __syncthreads();
    if (i < N_NODES)
        g_rowstart[i] = incl - v + warp_sums[wid];
}

// ---------------- K3b: scan the 49 block sums -> blockoff -------------------
__global__ void k_scan_block() {
    __shared__ int sh[64];
    int t = threadIdx.x;
    int v = (t < SCAN_BLOCKS) ? g_blocksum[t] : 0;
    sh[t] = v;
    __syncthreads();
    #pragma unroll
    for (int off = 1; off < 64; off <<= 1) {
        int x = (t >= off) ? sh[t - off] : 0;
        __syncthreads();
        sh[t] += x;
        __syncthreads();
    }
    if (t < SCAN_BLOCKS)
        g_blockoff[t] = sh[t] - v;   // exclusive
}

// ---------------- K4: scatter edges into CSR (no atomics) --------------------
__global__ void k_fill_csr(const int* __restrict__ src,
                           const int* __restrict__ dst) {
    int i = blockIdx.x * blockDim.x + threadIdx.x;
    if (i < N_EDGES) {
        int d = __ldg(&dst[i]);
        g_csr_src[row_begin(d) + g_epos[i]] = __ldg(&src[i]);
    }
}

// ======== K5: FUSED aggregate + FP16 MMA GEMM ================================
// 512 threads = 16 warps. Per block: 128 output rows.
//   iters 0,1: A = hn (cp.async from gmem, double-buffered)
//   then each warp aggregates 8 nodes' messages DIRECTLY into the A smem
//   buffers (lane L accumulates features 4L..4L+3 in fp32, stores half2s),
//   iters 2,3: A = msg (already in smem). g_msg never exists in gmem.
#define GBM 128
#define APAD 72    // A row stride in halfs
#define WPAD 264   // W row stride in halfs
#define SMEM_GEMM ((2 * GBM * APAD + 128 * WPAD) * 2)   // 104448 bytes

__global__ __launch_bounds__(512, 2)
void k_agg_gemm(const float* __restrict__ bias, // [128]
                float* __restrict__ out) {      // [N][128] fp32
    extern __shared__ __half sm[];
    __half* As = sm;                        // [2][128][APAD]
    __half* Ws = sm + 2 * GBM * APAD;       // [128][WPAD]

    int tid  = threadIdx.x;
    int warp = tid >> 5;
    int lane = tid & 31;
    int mg   = warp & 7;        // m-group: rows [mg*16, mg*16+16)
    int ng   = warp >> 3;       // n-group: cols [ng*64, ng*64+64)
    int rowBase = blockIdx.x * GBM;

    // ---- prologue: whole W (4096 uint4) + hn tile k0 (buf0), then k1 (buf1)
    #pragma unroll
    for (int it = 0; it < 8; it++) {
        int id = tid + it * 512;    // 0..4095
        int n  = id >> 5;
        int c8 = id & 31;
        cp_async16(&Ws[n * WPAD + c8 * 8], &g_W_h[n * 256 + c8 * 8]);
    }
    #pragma unroll
    for (int it = 0; it < 2; it++) {
        int id = tid + it * 512;
        int r  = id >> 3;
        int c8 = id & 7;
        int gr = rowBase + r;
        if (gr > N_NODES - 1) gr = N_NODES - 1;
        cp_async16(&As[r * APAD + c8 * 8], &g_hn_h[gr * D + c8 * 8]);
    }
    CP_COMMIT();
    #pragma unroll
    for (int it = 0; it < 2; it++) {
        int id = tid + it * 512;
        int r  = id >> 3;
        int c8 = id & 7;
        int gr = rowBase + r;
        if (gr > N_NODES - 1) gr = N_NODES - 1;
        cp_async16(&As[(GBM + r) * APAD + c8 * 8], &g_hn_h[gr * D + 64 + c8 * 8]);
    }
    CP_COMMIT();

    float acc[8][4];
    #pragma unroll
    for (int j = 0; j < 8; j++)
        #pragma unroll
        for (int c = 0; c < 4; c++) acc[j][c] = 0.f;

    int q = lane & 3;
    int g = lane >> 2;
    int r0 = mg * 16;

    auto mma_iter = [&](const __half* Ab, int kw) {
        #pragma unroll
        for (int k0 = 0; k0 < 64; k0 += 16) {
            uint32_t a0 = *(const uint32_t*)&Ab[(r0 + g) * APAD + k0 + 2 * q];
            uint32_t a1 = *(const uint32_t*)&Ab[(r0 + g + 8) * APAD + k0 + 2 * q];
            uint32_t a2 = *(const uint32_t*)&Ab[(r0 + g) * APAD + k0 + 2 * q + 8];
            uint32_t a3 = *(const uint32_t*)&Ab[(r0 + g + 8) * APAD + k0 + 2 * q + 8];
            #pragma unroll
            for (int j = 0; j < 8; j++) {
                int n = ng * 64 + j * 8 + g;
                uint32_t b0 = *(const uint32_t*)&Ws[n * WPAD + kw + k0 + 2 * q];
                uint32_t b1 = *(const uint32_t*)&Ws[n * WPAD + kw + k0 + 2 * q + 8];
                asm volatile(
                    "mma.sync.aligned.m16n8k16.row.col.f32.f16.f16.f32 "
                    "{%0,%1,%2,%3}, {%4,%5,%6,%7}, {%8,%9}, {%0,%1,%2,%3};"
                    : "+f"(acc[j][0]), "+f"(acc[j][1]),
                      "+f"(acc[j][2]), "+f"(acc[j][3])
                    : "r"(a0), "r"(a1), "r"(a2), "r"(a3), "r"(b0), "r"(b1));
            }
        }
    };

    // ---- hn half ----
    CP_WAIT(1);
    __syncthreads();
    mma_iter(&As[0], 0);
    CP_WAIT(0);
    __syncthreads();
    mma_iter(&As[GBM * APAD], 64);
    __syncthreads();   // all hn MMA reads done; A buffers free for msg

    // ---- aggregate msg for this block's 128 nodes into the A buffers ----
    // warp w handles rows w*8 .. w*8+7; lane L owns features 4L..4L+3.
    {
        #pragma unroll 1
        for (int j = 0; j < 8; j++) {
            int r = warp * 8 + j;
            int node = rowBase + r;
            float a0 = 0.f, a1 = 0.f, a2 = 0.f, a3 = 0.f;
            float b0 = 0.f, b1 = 0.f, b2 = 0.f, b3 = 0.f;
            if (node < N_NODES) {
                int e0 = row_begin(node);
                int e1 = (node + 1 < N_NODES) ? row_begin(node + 1) : N_EDGES;
                int e = e0;
                for (; e + 2 <= e1; e += 2) {
                    int s0 = __ldg(&g_csr_src[e]);
                    int s1 = __ldg(&g_csr_src[e + 1]);
                    float w0 = g_inv_out[s0];
                    float w1 = g_inv_out[s1];
                    uint2 u0 = *(const uint2*)&g_hn_h[s0 * D + lane * 4];
                    uint2 u1 = *(const uint2*)&g_hn_h[s1 * D + lane * 4];
                    float2 f00 = __half22float2(*(__half2*)&u0.x);
                    float2 f01 = __half22float2(*(__half2*)&u0.y);
                    float2 f10 = __half22float2(*(__half2*)&u1.x);
                    float2 f11 = __half22float2(*(__half2*)&u1.y);
                    a0 += f00.x * w0;  a1 += f00.y * w0;
                    a2 += f01.x * w0;  a3 += f01.y * w0;
                    b0 += f10.x * w1;  b1 += f10.y * w1;
                    b2 += f11.x * w1;  b3 += f11.y * w1;
                }
                if (e < e1) {
                    int s = __ldg(&g_csr_src[e]);
                    float w = g_inv_out[s];
                    uint2 u = *(const uint2*)&g_hn_h[s * D + lane * 4];
                    float2 f0 = __half22float2(*(__half2*)&u.x);
                    float2 f1 = __half22float2(*(__half2*)&u.y);
                    a0 += f0.x * w;  a1 += f0.y * w;
                    a2 += f1.x * w;  a3 += f1.y * w;
                }
                float wi = g_inv_in[node];
                a0 = (a0 + b0) * wi;  a1 = (a1 + b1) * wi;
                a2 = (a2 + b2) * wi;  a3 = (a3 + b3) * wi;
            }
            __half2 h0 = __float22half2_rn(make_float2(a0, a1));
            __half2 h1 = __float22half2_rn(make_float2(a2, a3));
            uint2 pack;
            pack.x = *(uint32_t*)&h0;
            pack.y = *(uint32_t*)&h1;
            // features 4L..4L+3: L<16 -> buf0 (k 0..63), L>=16 -> buf1
            __half* dstp = (lane < 16)
                ? &As[r * APAD + lane * 4]
                : &As[(GBM + r) * APAD + lane * 4 - 64];
            *(uint2*)dstp = pack;
        }
    }
    __syncthreads();

    // ---- msg half ----
    mma_iter(&As[0], 128);
    mma_iter(&As[GBM * APAD], 192);

    // ---- epilogue: bias + store ----
    int row0 = rowBase + mg * 16 + g;
    int row1 = row0 + 8;
    #pragma unroll
    for (int j = 0; j < 8; j++) {
        int col = ng * 64 + j * 8 + q * 2;
        float b0 = __ldg(&bias[col]);
        float b1 = __ldg(&bias[col + 1]);
        if (row0 < N_NODES) {
            float2 o = make_float2(acc[j][0] + b0, acc[j][1] + b1);
            *(float2*)&out[row0 * D + col] = o;
        }
        if (row1 < N_NODES) {
            float2 o = make_float2(acc[j][2] + b0, acc[j][3] + b1);
            *(float2*)&out[row1 * D + col] = o;
        }
    }
}

// ---------------- launcher (fork-join streams inside the capture) -----------
extern "C" void kernel_launch(void* const* d_in, const int* in_sizes, int n_in,
                              void* d_out, int out_size) {
    const float* h     = (const float*)d_in[0];
    const int*   ei    = (const int*)d_in[1];   // [2][E] int32
    const float* gamma = (const float*)d_in[2];
    const float* beta  = (const float*)d_in[3];
    const float* W     = (const float*)d_in[4];
    const float* bias  = (const float*)d_in[5];
    float*       out   = (float*)d_out;

    const int* src = ei;
    const int* dst = ei + N_EDGES;

    cudaFuncSetAttribute(k_agg_gemm, cudaFuncAttributeMaxDynamicSharedMemorySize,
                         SMEM_GEMM);

    cudaStream_t s2;
    cudaStreamCreateWithFlags(&s2, cudaStreamNonBlocking);
    cudaEvent_t evFork, evJoin;
    cudaEventCreateWithFlags(&evFork, cudaEventDisableTiming);
    cudaEventCreateWithFlags(&evJoin, cudaEventDisableTiming);

    // fork: s2 runs LN + W conversion concurrent with the edge chain
    cudaEventRecord(evFork, 0);
    cudaStreamWaitEvent(s2, evFork, 0);
    k_layernorm<<<(N_NODES * 32 + 255) / 256, 256, 0, s2>>>(h, gamma, beta);
    k_convw<<<((D * 2 * D / 4) + 255) / 256, 256, 0, s2>>>(W);
    cudaEventRecord(evJoin, s2);

    // main stream: edge chain (counters are pre-zeroed: zero-init at load,
    // re-zeroed by k_scan_local every launch)
    k_count<<<(N_EDGES + 255) / 256, 256>>>(src, dst);
    k_scan_local<<<SCAN_BLOCKS, 1024>>>();
    k_scan_block<<<1, 64>>>();
    k_fill_csr<<<(N_EDGES + 255) / 256, 256>>>(src, dst);

    // join, then fused aggregate+GEMM
    cudaStreamWaitEvent(0, evJoin, 0);
    k_agg_gemm<<<(N_NODES + GBM - 1) / GBM, 512, SMEM_GEMM>>>(bias, out);
}

// round 16
// speedup vs baseline: 1.2219x; 1.2219x over previous
#include <cuda_runtime.h>
#include <cuda_fp16.h>
#include <stdint.h>

#define N_NODES 50000
#define N_EDGES 600000
#define D 128
#define EPS 1e-5f
#define SCAN_BLOCKS 49   // ceil(50000/1024)

// ---------------- scratch (device globals; no allocations allowed) ----------
__device__ __half g_hn_h[N_NODES * D];   // layernormed features (fp16)
__device__ __half g_msg_h[N_NODES * D];  // aggregated message (fp16)
__device__ __half g_W_h[D * 2 * D];      // W fp16 (row-major [128][256])
__device__ int    g_counters[2 * N_NODES];  // [deg_in | deg_out]
__device__ float  g_inv_in[N_NODES];
__device__ float  g_inv_out[N_NODES];
__device__ int    g_rowstart[N_NODES];   // block-local exclusive scan of deg_in
__device__ int    g_blocksum[SCAN_BLOCKS];
__device__ int    g_blockoff[SCAN_BLOCKS];
__device__ int    g_epos[N_EDGES];       // per-edge rank within destination
__device__ int    g_csr_src[N_EDGES];

#define DEG_IN  (g_counters)
#define DEG_OUT (g_counters + N_NODES)

__device__ __forceinline__ int row_begin(int w) {
    return g_rowstart[w] + g_blockoff[w >> 10];
}

__device__ __forceinline__ void cp_async16(void* smem, const void* gmem) {
    uint32_t s = (uint32_t)__cvta_generic_to_shared(smem);
    asm volatile("cp.async.cg.shared.global [%0], [%1], 16;" :: "r"(s), "l"(gmem));
}
#define CP_COMMIT() asm volatile("cp.async.commit_group;")
#define CP_WAIT(n)  asm volatile("cp.async.wait_group %0;" :: "n"(n))

// ---------------- K1: degree counts + per-edge rank --------------------------
__global__ void k_count(const int* __restrict__ src,
                        const int* __restrict__ dst) {
    int i = blockIdx.x * blockDim.x + threadIdx.x;
    if (i < N_EDGES) {
        atomicAdd(&DEG_OUT[__ldg(&src[i])], 1);
        g_epos[i] = atomicAdd(&DEG_IN[__ldg(&dst[i])], 1);
    }
}

// ---------------- K1b: convert W to fp16 -------------------------------------
__global__ void k_convw(const float* __restrict__ W) {
    int i = blockIdx.x * blockDim.x + threadIdx.x;   // over float4 groups
    if (i < (D * 2 * D) / 4) {
        float4 v = *(const float4*)&W[i * 4];
        __half2 h0 = __float22half2_rn(make_float2(v.x, v.y));
        __half2 h1 = __float22half2_rn(make_float2(v.z, v.w));
        uint2 p;
        p.x = *(uint32_t*)&h0;
        p.y = *(uint32_t*)&h1;
        *(uint2*)&g_W_h[i * 4] = p;
    }
}

// ---------------- K2: LayerNorm (warp per row) -> fp16 (pure) ----------------
__global__ void k_layernorm(const float* __restrict__ h,
                            const float* __restrict__ gamma,
                            const float* __restrict__ beta) {
    int warp = (blockIdx.x * blockDim.x + threadIdx.x) >> 5;
    int lane = threadIdx.x & 31;
    if (warp >= N_NODES) return;

    float4 v = ((const float4*)h)[warp * 32 + lane];
    float s  = v.x + v.y + v.z + v.w;
    float sq = v.x * v.x + v.y * v.y + v.z * v.z + v.w * v.w;
    #pragma unroll
    for (int off = 16; off > 0; off >>= 1) {
        s  += __shfl_xor_sync(0xFFFFFFFF, s,  off);
        sq += __shfl_xor_sync(0xFFFFFFFF, sq, off);
    }
    float mu  = s * (1.0f / D);
    float var = sq * (1.0f / D) - mu * mu;
    float rs  = rsqrtf(var + EPS);

    float4 g = ((const float4*)gamma)[lane];
    float4 b = ((const float4*)beta)[lane];
    float ox = (v.x - mu) * rs * g.x + b.x;
    float oy = (v.y - mu) * rs * g.y + b.y;
    float oz = (v.z - mu) * rs * g.z + b.z;
    float ow = (v.w - mu) * rs * g.w + b.w;

    __half2 h0 = __float22half2_rn(make_float2(ox, oy));
    __half2 h1 = __float22half2_rn(make_float2(oz, ow));
    uint2 pack;
    pack.x = *(uint32_t*)&h0;
    pack.y = *(uint32_t*)&h1;
    ((uint2*)g_hn_h)[warp * 32 + lane] = pack;
}

// ---------------- K3a: block scan of deg_in + inv-sqrt degrees ---------------
__global__ __launch_bounds__(1024)
void k_scan_local() {
    __shared__ int warp_sums[32];
    int t = threadIdx.x;
    int i = blockIdx.x * 1024 + t;
    int lane = t & 31;
    int wid = t >> 5;

    int v = 0;
    if (i < N_NODES) {
        v = DEG_IN[i];
        int dout = DEG_OUT[i];
        g_inv_in[i]  = rsqrtf((float)(v    < 1 ? 1 : v));
        g_inv_out[i] = rsqrtf((float)(dout < 1 ? 1 : dout));
    }
    int incl = v;
    #pragma unroll
    for (int off = 1; off < 32; off <<= 1) {
        int n = __shfl_up_sync(0xFFFFFFFF, incl, off);
        if (lane >= off) incl += n;
    }
    if (lane == 31) warp_sums[wid] = incl;
    __syncthreads();
    if (wid == 0) {
        int ws = warp_sums[lane];
        int wi = ws;
        #pragma unroll
        for (int off = 1; off < 32; off <<= 1) {
            int n = __shfl_up_sync(0xFFFFFFFF, wi, off);
            if (lane >= off) wi += n;
        }
        warp_sums[lane] = wi - ws;   // exclusive warp offset
        if (lane == 31) g_blocksum[blockIdx.x] = wi;
    }
    __syncthreads();
    if (i < N_NODES)
        g_rowstart[i] = incl - v + warp_sums[wid];
}

// ---------------- K3b: scan the 49 block sums -> blockoff -------------------
__global__ void k_scan_block() {
    __shared__ int sh[64];
    int t = threadIdx.x;
    int v = (t < SCAN_BLOCKS) ? g_blocksum[t] : 0;
    sh[t] = v;
    __syncthreads();
    #pragma unroll
    for (int off = 1; off < 64; off <<= 1) {
        int x = (t >= off) ? sh[t - off] : 0;
        __syncthreads();
        sh[t] += x;
        __syncthreads();
    }
    if (t < SCAN_BLOCKS)
        g_blockoff[t] = sh[t] - v;   // exclusive
}

// ---------------- K4: scatter edges into CSR (no atomics) --------------------
__global__ void k_fill_csr(const int* __restrict__ src,
                           const int* __restrict__ dst) {
    int i = blockIdx.x * blockDim.x + threadIdx.x;
    if (i < N_EDGES) {
        int d = __ldg(&dst[i]);
        g_csr_src[row_begin(d) + g_epos[i]] = __ldg(&src[i]);
    }
}

// ---------------- K5: aggregation (warp per dst node, fp16, unroll 2) --------
__global__ void k_aggregate() {
    int warp = (blockIdx.x * blockDim.x + threadIdx.x) >> 5;
    int lane = threadIdx.x & 31;
    if (warp >= N_NODES) return;

    int e0 = row_begin(warp);
    int e1 = (warp + 1 < N_NODES) ? row_begin(warp + 1) : N_EDGES;

    float ax0 = 0.f, ay0 = 0.f, az0 = 0.f, aw0 = 0.f;
    float ax1 = 0.f, ay1 = 0.f, az1 = 0.f, aw1 = 0.f;
    int e = e0;
    for (; e + 2 <= e1; e += 2) {
        int s0 = __ldg(&g_csr_src[e]);
        int s1 = __ldg(&g_csr_src[e + 1]);
        float w0 = g_inv_out[s0];
        float w1 = g_inv_out[s1];
        uint2 u0 = ((const uint2*)g_hn_h)[s0 * 32 + lane];
        uint2 u1 = ((const uint2*)g_hn_h)[s1 * 32 + lane];
        float2 f00 = __half22float2(*(__half2*)&u0.x);
        float2 f01 = __half22float2(*(__half2*)&u0.y);
        float2 f10 = __half22float2(*(__half2*)&u1.x);
        float2 f11 = __half22float2(*(__half2*)&u1.y);
        ax0 += f00.x * w0;  ay0 += f00.y * w0;
        az0 += f01.x * w0;  aw0 += f01.y * w0;
        ax1 += f10.x * w1;  ay1 += f10.y * w1;
        az1 += f11.x * w1;  aw1 += f11.y * w1;
    }
    if (e < e1) {
        int s = __ldg(&g_csr_src[e]);
        float w = g_inv_out[s];
        uint2 u = ((const uint2*)g_hn_h)[s * 32 + lane];
        float2 f0 = __half22float2(*(__half2*)&u.x);
        float2 f1 = __half22float2(*(__half2*)&u.y);
        ax0 += f0.x * w;  ay0 += f0.y * w;
        az0 += f1.x * w;  aw0 += f1.y * w;
    }
    float wi = g_inv_in[warp];
    __half2 h0 = __float22half2_rn(make_float2((ax0 + ax1) * wi, (ay0 + ay1) * wi));
    __half2 h1 = __float22half2_rn(make_float2((az0 + az1) * wi, (aw0 + aw1) * wi));
    uint2 pack;
    pack.x = *(uint32_t*)&h0;
    pack.y = *(uint32_t*)&h1;
    ((uint2*)g_msg_h)[warp * 32 + lane] = pack;
}

// ---------------- K6: FP16 MMA GEMM, deep cp.async pipeline ------------------
// k-chunk 32, 4-buffer A ring, prefetch distance 3, W resident in smem.
// 256 threads = 8 warps, warp w owns rows [w*16, w*16+16) x all 128 cols.
#define GBM 128
#define AP32 40    // A tile row stride in halfs (32 + 8 pad, conflict-free)
#define WPAD 264   // W row stride in halfs
#define NTILE 8    // 8 k-chunks of 32 over the 256-wide [hn|msg] k dim
#define SMEM_GEMM (4 * GBM * AP32 * 2 + 128 * WPAD * 2)   // 108544 bytes

__global__ __launch_bounds__(256, 2)
void k_gemm(const float* __restrict__ bias, // [128]
            float* __restrict__ out) {      // [N][128] fp32
    extern __shared__ __half sm[];
    __half* As = sm;                        // [4][128][AP32] ring
    __half* Ws = sm + 4 * GBM * AP32;       // [128][WPAD]

    int tid  = threadIdx.x;
    int warp = tid >> 5;
    int lane = tid & 31;
    int rowBase = blockIdx.x * GBM;

    // stage k-chunk i (128 rows x 32 halfs = 512 cp16) into ring slot i&3
    auto issue_a = [&](int i) {
        const __half* Asrc = (i < 4) ? g_hn_h : g_msg_h;
        int kOff = (i * 32) & (D - 1);
        int slot = i & 3;
        #pragma unroll
        for (int it = 0; it < 2; it++) {
            int id = tid + it * 256;    // 0..511
            int r  = id >> 2;           // 0..127
            int c  = id & 3;            // 0..3 (8-half groups)
            int gr = rowBase + r;
            if (gr > N_NODES - 1) gr = N_NODES - 1;   // clamp; result discarded
            cp_async16(&As[(slot * GBM + r) * AP32 + c * 8],
                       &Asrc[gr * D + kOff + c * 8]);
        }
    };

    // prologue: W (4096 cp16) + tile0 as group0; tiles 1,2 as groups 1,2
    #pragma unroll
    for (int it = 0; it < 16; it++) {
        int id = tid + it * 256;    // 0..4095
        int n  = id >> 5;
        int c8 = id & 31;
        cp_async16(&Ws[n * WPAD + c8 * 8], &g_W_h[n * 256 + c8 * 8]);
    }
    issue_a(0);
    CP_COMMIT();
    issue_a(1);
    CP_COMMIT();
    issue_a(2);
    CP_COMMIT();

    float acc[16][4];
    #pragma unroll
    for (int j = 0; j < 16; j++)
        #pragma unroll
        for (int c = 0; c < 4; c++) acc[j][c] = 0.f;

    int q = lane & 3;
    int g = lane >> 2;
    int r0 = warp * 16;

    for (int i = 0; i < NTILE; i++) {
        if (i < NTILE - 3) {            // i = 0..4 issue tiles 3..7
            issue_a(i + 3);
            CP_COMMIT();
            CP_WAIT(3);                 // tile i (and W) landed
        } else if (i == NTILE - 3) {
            CP_WAIT(2);
        } else if (i == NTILE - 2) {
            CP_WAIT(1);
        } else {
            CP_WAIT(0);
        }
        __syncthreads();

        const __half* Ab = &As[(i & 3) * GBM * AP32];
        int kw = i * 32;
        #pragma unroll
        for (int k0 = 0; k0 < 32; k0 += 16) {
            uint32_t a0 = *(const uint32_t*)&Ab[(r0 + g) * AP32 + k0 + 2 * q];
            uint32_t a1 = *(const uint32_t*)&Ab[(r0 + g + 8) * AP32 + k0 + 2 * q];
            uint32_t a2 = *(const uint32_t*)&Ab[(r0 + g) * AP32 + k0 + 2 * q + 8];
            uint32_t a3 = *(const uint32_t*)&Ab[(r0 + g + 8) * AP32 + k0 + 2 * q + 8];
            #pragma unroll
            for (int j = 0; j < 16; j++) {
                int n = j * 8 + g;
                uint32_t b0 = *(const uint32_t*)&Ws[n * WPAD + kw + k0 + 2 * q];
                uint32_t b1 = *(const uint32_t*)&Ws[n * WPAD + kw + k0 + 2 * q + 8];
                asm volatile(
                    "mma.sync.aligned.m16n8k16.row.col.f32.f16.f16.f32 "
                    "{%0,%1,%2,%3}, {%4,%5,%6,%7}, {%8,%9}, {%0,%1,%2,%3};"
                    : "+f"(acc[j][0]), "+f"(acc[j][1]),
                      "+f"(acc[j][2]), "+f"(acc[j][3])
                    : "r"(a0), "r"(a1), "r"(a2), "r"(a3), "r"(b0), "r"(b1));
            }
        }
        __syncthreads();   // reads done; slot i&3 may be overwritten at i+1
    }

    // epilogue: bias + store
    int row0 = rowBase + warp * 16 + g;
    int row1 = row0 + 8;
    #pragma unroll
    for (int j = 0; j < 16; j++) {
        int col = j * 8 + q * 2;
        float b0 = __ldg(&bias[col]);
        float b1 = __ldg(&bias[col + 1]);
        if (row0 < N_NODES) {
            float2 o = make_float2(acc[j][0] + b0, acc[j][1] + b1);
            *(float2*)&out[row0 * D + col] = o;
        }
        if (row1 < N_NODES) {
            float2 o = make_float2(acc[j][2] + b0, acc[j][3] + b1);
            *(float2*)&out[row1 * D + col] = o;
        }
    }
}

// ---------------- launcher (fork-join streams inside the capture) -----------
extern "C" void kernel_launch(void* const* d_in, const int* in_sizes, int n_in,
                              void* d_out, int out_size) {
    const float* h     = (const float*)d_in[0];
    const int*   ei    = (const int*)d_in[1];   // [2][E] int32
    const float* gamma = (const float*)d_in[2];
    const float* beta  = (const float*)d_in[3];
    const float* W     = (const float*)d_in[4];
    const float* bias  = (const float*)d_in[5];
    float*       out   = (float*)d_out;

    const int* src = ei;
    const int* dst = ei + N_EDGES;

    cudaFuncSetAttribute(k_gemm, cudaFuncAttributeMaxDynamicSharedMemorySize,
                         SMEM_GEMM);

    cudaStream_t s2;
    cudaStreamCreateWithFlags(&s2, cudaStreamNonBlocking);
    cudaEvent_t evFork, evJoin;
    cudaEventCreateWithFlags(&evFork, cudaEventDisableTiming);
    cudaEventCreateWithFlags(&evJoin, cudaEventDisableTiming);

    void* counters_ptr = nullptr;
    cudaGetSymbolAddress(&counters_ptr, g_counters);
    cudaMemsetAsync(counters_ptr, 0, 2 * N_NODES * sizeof(int), 0);

    // fork: s2 runs LN + W conversion concurrent with the edge chain
    cudaEventRecord(evFork, 0);
    cudaStreamWaitEvent(s2, evFork, 0);
    k_layernorm<<<(N_NODES * 32 + 255) / 256, 256, 0, s2>>>(h, gamma, beta);
    k_convw<<<((D * 2 * D / 4) + 255) / 256, 256, 0, s2>>>(W);
    cudaEventRecord(evJoin, s2);

    // main stream: edge chain
    k_count<<<(N_EDGES + 255) / 256, 256>>>(src, dst);
    k_scan_local<<<SCAN_BLOCKS, 1024>>>();
    k_scan_block<<<1, 64>>>();
    k_fill_csr<<<(N_EDGES + 255) / 256, 256>>>(src, dst);

    // join, then aggregate + GEMM
    cudaStreamWaitEvent(0, evJoin, 0);
    k_aggregate<<<(N_NODES * 32 + 255) / 256, 256>>>();
    k_gemm<<<(N_NODES + GBM - 1) / GBM, 256, SMEM_GEMM>>>(bias, out);
}